// round 2
// baseline (speedup 1.0000x reference)
#include <cuda_runtime.h>
#include <math.h>

#define DM     1024
#define HEADS  16
#define DKH    64
#define BATCH  2
#define SEQ    2048
#define MTOT   (BATCH*SEQ)

// Scratch (static device globals — no allocation inside kernel_launch)
__device__ float g_q[BATCH*HEADS*SEQ*DKH];    // [b][h][s][d]
__device__ float g_k[BATCH*HEADS*SEQ*DKH];
__device__ float g_v[BATCH*HEADS*SEQ*DKH];
__device__ float g_ctx[BATCH*SEQ*DM];         // [b][s][h*64+d]

// ---------------------------------------------------------------------------
// GEMM: C[m][n] = sum_d A[m][d] * W[n][d] + bias[n]
// A: [M][1024] row-major, W: [1024][1024] row-major (both K-contiguous).
// MODE 0: out plain [m][n]   (final projection -> d_out)
// MODE 1: out head layout [b][h][s][d] with h = blockIdx.y (BN == DKH == 64)
// Tiling: BM=BN=64, BK=16, 256 threads, 4x4 microtile per thread.
// ---------------------------------------------------------------------------
template<int MODE>
__global__ __launch_bounds__(256)
void gemm64(const float* __restrict__ A, const float* __restrict__ W,
            const float* __restrict__ bias, float* __restrict__ out)
{
    __shared__ float As[16][68];   // [k][m], padded
    __shared__ float Bs[16][68];   // [k][n], padded

    const int tid = threadIdx.x;
    const int tx  = tid & 15;       // n-direction
    const int ty  = tid >> 4;       // m-direction
    const int m0  = blockIdx.x * 64;
    const int n0  = blockIdx.y * 64;

    const int lr = tid >> 2;        // 0..63 : row of the 64x16 load tile
    const int lc = (tid & 3) * 4;   // 0,4,8,12 : k-col of the float4

    const float* Ap = A + (size_t)(m0 + lr) * DM + lc;
    const float* Wp = W + (size_t)(n0 + lr) * DM + lc;

    float acc[4][4] = {};

    for (int k0 = 0; k0 < DM; k0 += 16) {
        const float4 av = *(const float4*)(Ap + k0);
        const float4 wv = *(const float4*)(Wp + k0);
        __syncthreads();
        As[lc+0][lr] = av.x; As[lc+1][lr] = av.y; As[lc+2][lr] = av.z; As[lc+3][lr] = av.w;
        Bs[lc+0][lr] = wv.x; Bs[lc+1][lr] = wv.y; Bs[lc+2][lr] = wv.z; Bs[lc+3][lr] = wv.w;
        __syncthreads();

        #pragma unroll
        for (int kk = 0; kk < 16; kk++) {
            const float4 a = *(const float4*)&As[kk][ty*4];
            const float4 b = *(const float4*)&Bs[kk][tx*4];
            acc[0][0] += a.x*b.x; acc[0][1] += a.x*b.y; acc[0][2] += a.x*b.z; acc[0][3] += a.x*b.w;
            acc[1][0] += a.y*b.x; acc[1][1] += a.y*b.y; acc[1][2] += a.y*b.z; acc[1][3] += a.y*b.w;
            acc[2][0] += a.z*b.x; acc[2][1] += a.z*b.y; acc[2][2] += a.z*b.z; acc[2][3] += a.z*b.w;
            acc[3][0] += a.w*b.x; acc[3][1] += a.w*b.y; acc[3][2] += a.w*b.z; acc[3][3] += a.w*b.w;
        }
    }

    const float4 bv = *(const float4*)(bias + n0 + tx*4);

    #pragma unroll
    for (int i = 0; i < 4; i++) {
        const int m = m0 + ty*4 + i;
        float4 r;
        r.x = acc[i][0] + bv.x;
        r.y = acc[i][1] + bv.y;
        r.z = acc[i][2] + bv.z;
        r.w = acc[i][3] + bv.w;
        if (MODE == 0) {
            *(float4*)(out + (size_t)m * DM + n0 + tx*4) = r;
        } else {
            const int b = m >> 11;            // /SEQ
            const int s = m & (SEQ - 1);
            const int h = n0 >> 6;            // BN == DKH
            *(float4*)(out + (((size_t)(b*HEADS + h))*SEQ + s)*DKH + tx*4) = r;
        }
    }
}

// ---------------------------------------------------------------------------
// Flash-style attention: one CTA = one (b,h) x 64-row Q block.
// smem: Qt [d][i] 16KB, KV (Kt [d][j] then Vs [k][d]) 16KB, Ps [i][k] 16KB.
// Online softmax, O accumulated in registers (4x4 per thread).
// ---------------------------------------------------------------------------
__global__ __launch_bounds__(256)
void attn_kernel(const int* __restrict__ mask, float* __restrict__ ctx)
{
    __shared__ float Qt[64][64];   // [d][qi]
    __shared__ float KV[64][64];   // phase 1: Kt [d][kj]; phase 2: Vs [k][d]
    __shared__ float Ps[64][64];   // [qi][k]

    const int tid = threadIdx.x;
    const int tx  = tid & 15;
    const int ty  = tid >> 4;
    const int bh  = blockIdx.y;
    const int b   = bh >> 4;
    const int h   = bh & 15;
    const int q0  = blockIdx.x * 64;

    const float* qbase = g_q + (size_t)bh * SEQ * DKH;
    const float* kbase = g_k + (size_t)bh * SEQ * DKH;
    const float* vbase = g_v + (size_t)bh * SEQ * DKH;
    const int*   mbase = mask + (size_t)b * SEQ * SEQ + (size_t)q0 * SEQ;

    // Load Q block transposed: Qt[d][i]
    #pragma unroll
    for (int it = 0; it < 4; it++) {
        const int idx = tid + it * 256;
        const int row = idx >> 4;
        const int c4  = (idx & 15) * 4;
        const float4 v = *(const float4*)(qbase + (size_t)(q0 + row) * DKH + c4);
        Qt[c4+0][row] = v.x; Qt[c4+1][row] = v.y; Qt[c4+2][row] = v.z; Qt[c4+3][row] = v.w;
    }

    float o[4][4] = {};
    float mrow[4] = {-1e30f, -1e30f, -1e30f, -1e30f};
    float lrow[4] = {};

    for (int k0 = 0; k0 < SEQ; k0 += 64) {
        __syncthreads();   // previous iteration done with KV (as Vs) and Ps
        // Load K block transposed: KV[d][j]
        #pragma unroll
        for (int it = 0; it < 4; it++) {
            const int idx = tid + it * 256;
            const int row = idx >> 4;
            const int c4  = (idx & 15) * 4;
            const float4 v = *(const float4*)(kbase + (size_t)(k0 + row) * DKH + c4);
            KV[c4+0][row] = v.x; KV[c4+1][row] = v.y; KV[c4+2][row] = v.z; KV[c4+3][row] = v.w;
        }
        __syncthreads();

        // S = Q K^T (4x4 per thread)
        float s[4][4] = {};
        #pragma unroll 16
        for (int d = 0; d < 64; d++) {
            const float4 a = *(const float4*)&Qt[d][ty*4];
            const float4 c = *(const float4*)&KV[d][tx*4];
            s[0][0] += a.x*c.x; s[0][1] += a.x*c.y; s[0][2] += a.x*c.z; s[0][3] += a.x*c.w;
            s[1][0] += a.y*c.x; s[1][1] += a.y*c.y; s[1][2] += a.y*c.z; s[1][3] += a.y*c.w;
            s[2][0] += a.z*c.x; s[2][1] += a.z*c.y; s[2][2] += a.z*c.z; s[2][3] += a.z*c.w;
            s[3][0] += a.w*c.x; s[3][1] += a.w*c.y; s[3][2] += a.w*c.z; s[3][3] += a.w*c.w;
        }

        // scale + mask
        #pragma unroll
        for (int i = 0; i < 4; i++) {
            #pragma unroll
            for (int j = 0; j < 4; j++) {
                const float sv = s[i][j] * 0.125f;   // 1/sqrt(64)
                const int mv = mbase[(size_t)(ty*4 + i) * SEQ + k0 + tx*4 + j];
                s[i][j] = (mv == 0) ? -1e9f : sv;
            }
        }

        // online softmax per row; row group = 16 lanes sharing ty (width-16 shuffles)
        #pragma unroll
        for (int r = 0; r < 4; r++) {
            float mx = fmaxf(fmaxf(s[r][0], s[r][1]), fmaxf(s[r][2], s[r][3]));
            #pragma unroll
            for (int t = 8; t > 0; t >>= 1)
                mx = fmaxf(mx, __shfl_xor_sync(0xffffffffu, mx, t, 16));
            const float nm   = fmaxf(mrow[r], mx);
            const float corr = __expf(mrow[r] - nm);
            mrow[r] = nm;

            const float p0 = __expf(s[r][0] - nm);
            const float p1 = __expf(s[r][1] - nm);
            const float p2 = __expf(s[r][2] - nm);
            const float p3 = __expf(s[r][3] - nm);
            float rs = p0 + p1 + p2 + p3;
            #pragma unroll
            for (int t = 8; t > 0; t >>= 1)
                rs += __shfl_xor_sync(0xffffffffu, rs, t, 16);
            lrow[r] = lrow[r] * corr + rs;

            o[r][0] *= corr; o[r][1] *= corr; o[r][2] *= corr; o[r][3] *= corr;

            Ps[ty*4 + r][tx*4 + 0] = p0;
            Ps[ty*4 + r][tx*4 + 1] = p1;
            Ps[ty*4 + r][tx*4 + 2] = p2;
            Ps[ty*4 + r][tx*4 + 3] = p3;
        }
        __syncthreads();   // Kt reads & Ps writes complete

        // Load V block natural: KV[k][d]  (reuses Kt buffer)
        #pragma unroll
        for (int it = 0; it < 4; it++) {
            const int idx = tid + it * 256;
            const int row = idx >> 4;
            const int c4  = (idx & 15) * 4;
            *(float4*)&KV[row][c4] = *(const float4*)(vbase + (size_t)(k0 + row) * DKH + c4);
        }
        __syncthreads();

        // O += P V
        #pragma unroll 8
        for (int k = 0; k < 64; k++) {
            const float4 vv = *(const float4*)&KV[k][tx*4];
            #pragma unroll
            for (int i = 0; i < 4; i++) {
                const float p = Ps[ty*4 + i][k];
                o[i][0] += p * vv.x; o[i][1] += p * vv.y;
                o[i][2] += p * vv.z; o[i][3] += p * vv.w;
            }
        }
    }

    // Normalize and write ctx in [b][s][h*64+d] layout
    #pragma unroll
    for (int i = 0; i < 4; i++) {
        const float inv = 1.0f / lrow[i];
        float4 r;
        r.x = o[i][0] * inv; r.y = o[i][1] * inv;
        r.z = o[i][2] * inv; r.w = o[i][3] * inv;
        const int s = q0 + ty*4 + i;
        *(float4*)(g_ctx + ((size_t)(b*SEQ) + s) * DM + h*DKH + tx*4) = r;
    }
}

// ---------------------------------------------------------------------------
extern "C" void kernel_launch(void* const* d_in, const int* in_sizes, int n_in,
                              void* d_out, int out_size)
{
    (void)in_sizes; (void)n_in; (void)out_size;
    const float* hid  = (const float*)d_in[0];
    const int*   mask = (const int*)  d_in[1];
    const float* Wq   = (const float*)d_in[2];
    const float* bq   = (const float*)d_in[3];
    const float* Wk   = (const float*)d_in[4];
    const float* bk   = (const float*)d_in[5];
    const float* Wv   = (const float*)d_in[6];
    const float* bv   = (const float*)d_in[7];
    const float* Wo   = (const float*)d_in[8];
    const float* bo   = (const float*)d_in[9];
    float* out = (float*)d_out;

    float *qp, *kp, *vp, *cp;
    cudaGetSymbolAddress((void**)&qp, g_q);
    cudaGetSymbolAddress((void**)&kp, g_k);
    cudaGetSymbolAddress((void**)&vp, g_v);
    cudaGetSymbolAddress((void**)&cp, g_ctx);

    const dim3 gproj(MTOT/64, DM/64);       // 64 x 16
    gemm64<1><<<gproj, 256>>>(hid, Wq, bq, qp);
    gemm64<1><<<gproj, 256>>>(hid, Wk, bk, kp);
    gemm64<1><<<gproj, 256>>>(hid, Wv, bv, vp);

    attn_kernel<<<dim3(SEQ/64, BATCH*HEADS), 256>>>(mask, cp);

    gemm64<0><<<gproj, 256>>>(cp, Wo, bo, out);
}